// round 17
// baseline (speedup 1.0000x reference)
#include <cuda_runtime.h>
#include <cstdint>

#define Nn   64
#define Cc   256
#define HWs  3136
#define Gg   16
#define Mf   200704.0f
#define EPSf 1e-3f

#define SLICES 148
#define HW4       784
#define TOT_TASKS (Nn * Gg * HW4)
#define APPLY_BLOCKS 296

// Scratch (static device globals — no allocation)
__device__ float g_sig[Gg][SLICES][16][16];
__device__ float g_sum[Gg][SLICES][16];
__device__ float g_A[Gg][16][16];
__device__ float g_beta[Gg][16];

// ---------------- helpers ----------------
__device__ __forceinline__ uint32_t to_tf32(float f) {
    uint32_t u;
    asm("cvt.rna.tf32.f32 %0, %1;" : "=r"(u) : "f"(f));
    return u;
}

__device__ __forceinline__ void mma_tf32(float* c, uint32_t a0, uint32_t a1,
                                         uint32_t a2, uint32_t a3,
                                         uint32_t b0, uint32_t b1) {
    asm("mma.sync.aligned.m16n8k8.row.col.f32.tf32.tf32.f32 "
        "{%0,%1,%2,%3}, {%4,%5,%6,%7}, {%8,%9}, {%0,%1,%2,%3};"
        : "+f"(c[0]), "+f"(c[1]), "+f"(c[2]), "+f"(c[3])
        : "r"(a0), "r"(a1), "r"(a2), "r"(a3), "r"(b0), "r"(b1));
}

// ---------------------------------------------------------------------------
// Kernel 1: Gram via warp-level tf32 mma.sync (verified R11). 148 x 512.
// Default-policy loads: X lines stay in L2 so k_apply can hit them.
// ---------------------------------------------------------------------------
__global__ __launch_bounds__(512, 1) void k_stats(const float* __restrict__ X) {
    const int s = blockIdx.x;
    const int g = threadIdx.x >> 5;
    const int lane = threadIdx.x & 31;
    const int row = lane >> 2, q = lane & 3;

    const int units = 21 + (s < 28 ? 1 : 0);
    const int p0 = s * 1344 + (s < 28 ? s : 28) * 64;

    float c[8];
#pragma unroll
    for (int i = 0; i < 8; i++) c[i] = 0.f;
    float slo = 0.f, shi = 0.f;

    int n  = p0 / HWs;
    int hw = p0 - n * HWs;
    const float* b0 = X + (size_t)n * Cc * HWs
                        + (size_t)(g * 16 + row) * HWs + hw + 4 * q;

    for (int u = 0; u < units; u++) {
        const float* b1 = b0 + 8 * HWs;

        float4 vlo[4], vhi[4];
#pragma unroll
        for (int i = 0; i < 4; i++) vlo[i] = *(const float4*)(b0 + 16 * i);
#pragma unroll
        for (int i = 0; i < 4; i++) vhi[i] = *(const float4*)(b1 + 16 * i);

#pragma unroll
        for (int i = 0; i < 4; i++) {
            slo += (vlo[i].x + vlo[i].y) + (vlo[i].z + vlo[i].w);
            shi += (vhi[i].x + vhi[i].y) + (vhi[i].z + vhi[i].w);

            uint32_t a0 = to_tf32(vlo[i].x), a1 = to_tf32(vhi[i].x);
            uint32_t a2 = to_tf32(vlo[i].y), a3 = to_tf32(vhi[i].y);
            mma_tf32(c,     a0, a1, a2, a3, a0, a2);
            mma_tf32(c + 4, a0, a1, a2, a3, a1, a3);

            uint32_t e0 = to_tf32(vlo[i].z), e1 = to_tf32(vhi[i].z);
            uint32_t e2 = to_tf32(vlo[i].w), e3 = to_tf32(vhi[i].w);
            mma_tf32(c,     e0, e1, e2, e3, e0, e2);
            mma_tf32(c + 4, e0, e1, e2, e3, e1, e3);
        }

        hw += 64;
        if (hw == HWs) {
            hw = 0;
            b0 += 64 + (size_t)(Cc - 1) * HWs;
        } else {
            b0 += 64;
        }
    }

    slo += __shfl_xor_sync(0xffffffffu, slo, 1);
    slo += __shfl_xor_sync(0xffffffffu, slo, 2);
    shi += __shfl_xor_sync(0xffffffffu, shi, 1);
    shi += __shfl_xor_sync(0xffffffffu, shi, 2);
    if (q == 0) {
        g_sum[g][s][row]     = slo;
        g_sum[g][s][row + 8] = shi;
    }

    *(float2*)&g_sig[g][s][row][2 * q]         = make_float2(c[0], c[1]);
    *(float2*)&g_sig[g][s][row + 8][2 * q]     = make_float2(c[2], c[3]);
    *(float2*)&g_sig[g][s][row][8 + 2 * q]     = make_float2(c[4], c[5]);
    *(float2*)&g_sig[g][s][row + 8][8 + 2 * q] = make_float2(c[6], c[7]);
}

// ---------------------------------------------------------------------------
// Kernel 2: partials -> sigma -> Newton-Schulz -> A, beta. 16 x 256.
// ---------------------------------------------------------------------------
__global__ __launch_bounds__(256, 1) void k_wm(const float* __restrict__ wgt,
                                               const float* __restrict__ bia) {
    const int g = blockIdx.x;
    const int t = threadIdx.x;
    const int r = t >> 4, c = t & 15;

    __shared__ float meanS[16];
    __shared__ float sig[16][17], P[16][17], T1[16][17], T2[16][17];

    float sv = 0.f;
    for (int b = 0; b < SLICES; b++) sv += g_sig[g][b][r][c];

    if (t < 16) {
        float a = 0.f;
        for (int b = 0; b < SLICES; b++) a += g_sum[g][b][t];
        meanS[t] = a * (1.0f / Mf);
    }
    __syncthreads();

    sv = sv * (1.0f / Mf) - meanS[r] * meanS[c] + ((r == c) ? EPSf : 0.f);
    sig[r][c] = sv;
    __syncthreads();

    float tr = 0.f;
#pragma unroll
    for (int k = 0; k < 16; k++) tr += sig[k][k];
    __syncthreads();

    sig[r][c] = sv / tr;
    P[r][c] = (r == c) ? 1.f : 0.f;
    __syncthreads();

    for (int it = 0; it < 10; it++) {
        float d1 = 0.f;
#pragma unroll
        for (int k = 0; k < 16; k++) d1 += P[r][k] * P[k][c];
        T1[r][c] = d1;
        __syncthreads();
        float d2 = 0.f;
#pragma unroll
        for (int k = 0; k < 16; k++) d2 += T1[r][k] * P[k][c];
        T2[r][c] = d2;
        __syncthreads();
        float d3 = 0.f;
#pragma unroll
        for (int k = 0; k < 16; k++) d3 += T2[r][k] * sig[k][c];
        P[r][c] = 1.5f * P[r][c] - 0.5f * d3;
        __syncthreads();
    }

    const float wmv = P[r][c] * rsqrtf(tr);
    const float Av  = wgt[g * 16 + r] * wmv;
    g_A[g][r][c] = Av;
    T1[r][c] = Av * meanS[c];
    __syncthreads();
    if (t < 16) {
        float acc = bia[g * 16 + t];
#pragma unroll
        for (int d = 0; d < 16; d++) acc -= T1[t][d];
        g_beta[g][t] = acc;
    }
}

// ---------------------------------------------------------------------------
// Kernel 3: apply out = A*v + beta. Scalar fp32, LDS.128 A-quads. Default
// loads (hit X lines left in L2 by k_stats); .cs stores (Y is dead data,
// evict-first to preserve X residency). 296 x 256, occ 2.
// ---------------------------------------------------------------------------
__global__ __launch_bounds__(256, 2) void k_apply(const float* __restrict__ X,
                                                  float* __restrict__ Y) {
    __shared__ float As[Gg * 256];   // As[g*256 + c*16 + d]
    __shared__ float Bs[Gg * 16];

    for (int i = threadIdx.x; i < Gg * 256; i += 256)
        As[i] = ((const float*)g_A)[i];
    Bs[threadIdx.x] = ((const float*)g_beta)[threadIdx.x];
    __syncthreads();

    const int stride = APPLY_BLOCKS * 256;
    for (int t = blockIdx.x * 256 + threadIdx.x; t < TOT_TASKS; t += stride) {
        const int col = t / HW4;
        const int q   = t - col * HW4;
        const int g   = col & 15;
        const int n   = col >> 4;

        const size_t off = ((size_t)n * Cc + (size_t)g * 16) * HWs;
        const float4* xb = (const float4*)(X + off) + q;
        float4*       yb = (float4*)(Y + off) + q;
        const float*  Ag = As + g * 256;
        const float*  Bg = Bs + g * 16;

        float4 acc[16];
#pragma unroll
        for (int c = 0; c < 16; c++) {
            const float b = Bg[c];
            acc[c].x = b; acc[c].y = b; acc[c].z = b; acc[c].w = b;
        }

#pragma unroll
        for (int dq = 0; dq < 4; dq++) {
            const float4 xv0 = xb[(4 * dq + 0) * HW4];
            const float4 xv1 = xb[(4 * dq + 1) * HW4];
            const float4 xv2 = xb[(4 * dq + 2) * HW4];
            const float4 xv3 = xb[(4 * dq + 3) * HW4];
#pragma unroll
            for (int c = 0; c < 16; c++) {
                const float4 a4 = *(const float4*)(Ag + c * 16 + 4 * dq);
                acc[c].x = fmaf(a4.x, xv0.x, acc[c].x);
                acc[c].y = fmaf(a4.x, xv0.y, acc[c].y);
                acc[c].z = fmaf(a4.x, xv0.z, acc[c].z);
                acc[c].w = fmaf(a4.x, xv0.w, acc[c].w);
                acc[c].x = fmaf(a4.y, xv1.x, acc[c].x);
                acc[c].y = fmaf(a4.y, xv1.y, acc[c].y);
                acc[c].z = fmaf(a4.y, xv1.z, acc[c].z);
                acc[c].w = fmaf(a4.y, xv1.w, acc[c].w);
                acc[c].x = fmaf(a4.z, xv2.x, acc[c].x);
                acc[c].y = fmaf(a4.z, xv2.y, acc[c].y);
                acc[c].z = fmaf(a4.z, xv2.z, acc[c].z);
                acc[c].w = fmaf(a4.z, xv2.w, acc[c].w);
                acc[c].x = fmaf(a4.w, xv3.x, acc[c].x);
                acc[c].y = fmaf(a4.w, xv3.y, acc[c].y);
                acc[c].z = fmaf(a4.w, xv3.z, acc[c].z);
                acc[c].w = fmaf(a4.w, xv3.w, acc[c].w);
            }
        }
#pragma unroll
        for (int c = 0; c < 16; c++)
            __stcs(yb + c * HW4, acc[c]);
    }
}

// ---------------------------------------------------------------------------
extern "C" void kernel_launch(void* const* d_in, const int* in_sizes, int n_in,
                              void* d_out, int out_size) {
    const float* X = (const float*)d_in[0];
    const float* W = (const float*)d_in[1];
    const float* B = (const float*)d_in[2];
    float* Y = (float*)d_out;

    k_stats<<<SLICES, 512>>>(X);
    k_wm<<<Gg, 256>>>(W, B);
    k_apply<<<APPLY_BLOCKS, 256>>>(X, Y);
}